// round 17
// baseline (speedup 1.0000x reference)
#include <cuda_runtime.h>
#include <cstdint>

#define NCEN   512
#define NKEYS  262144          // 512*512
#define EC1    130817          // E_COARSE + 1
#define NN     100000
#define EE     800000
#define HH     128

// output offsets (float elements)
#define O_NODE  0
#define O_ATTR  131072
#define O_EDGES 33620224
#define O_CCI   33881858
#define O_DIST  33981858

// ---------------- device scratch (no allocations allowed) ----------------
__device__ int g_cnt_key[NKEYS];
__device__ int g_cursor[NKEYS];
__device__ int g_key[EE];
__device__ int g_edge_sorted[EE];
__device__ int g_slot_cnt[EC1];
__device__ int g_slot_off[EC1];
__device__ int g_blk_occ[512];
__device__ int g_blk_cnt[512];
__device__ int g_cnt_node[NCEN];
__device__ int g_nuniq;
__device__ int g_totedge;
__device__ int g_bar[8];
__device__ int g_work;

// ---------------- helpers ----------------
__device__ __forceinline__ void fma2(unsigned long long &acc,
                                     unsigned long long a,
                                     unsigned long long b) {
    asm("fma.rn.f32x2 %0, %1, %2, %0;" : "+l"(acc) : "l"(a), "l"(b));
}
__device__ __forceinline__ float2 unpack2(unsigned long long v) {
    float2 r;
    asm("mov.b64 {%0, %1}, %2;" : "=f"(r.x), "=f"(r.y) : "l"(v));
    return r;
}
__device__ __forceinline__ unsigned long long pack2(float a, float b) {
    unsigned long long p;
    asm("mov.b64 %0, {%1, %2};" : "=l"(p) : "f"(a), "f"(b));
    return p;
}
__device__ __forceinline__ void red_add_v2(float* p, float a, float b) {
    asm volatile("red.global.add.v2.f32 [%0], {%1,%2};"
                 :: "l"(p), "f"(a), "f"(b) : "memory");
}
__device__ __forceinline__ int wscan_incl(int v, int lane) {
#pragma unroll
    for (int o = 1; o < 32; o <<= 1) {
        int u = __shfl_up_sync(0xffffffffu, v, o);
        if (lane >= o) v += u;
    }
    return v;
}
__device__ __forceinline__ void cp16(uint32_t dst, const void* src) {
    asm volatile("cp.async.cg.shared.global [%0], [%1], 16;"
                 :: "r"(dst), "l"(src) : "memory");
}
#define CP_COMMIT() asm volatile("cp.async.commit_group;" ::: "memory")
#define CP_WAIT(n)  asm volatile("cp.async.wait_group %0;" :: "n"(n) : "memory")

// Barrier among co-resident blocks of ONE grid (backward deps only).
__device__ __forceinline__ void gbarrier(int idx, int expect, bool spin) {
    __threadfence();
    __syncthreads();
    if (threadIdx.x == 0) {
        atomicAdd(&g_bar[idx], 1);
        if (spin) {
            while (((volatile int*)g_bar)[idx] < expect) __nanosleep(64);
        }
    }
    __syncthreads();
    __threadfence();
}
// Bounded cross-kernel wait: returns false on timeout (never deadlocks,
// even when a profiler serializes kernel execution).
__device__ __forceinline__ bool wait_flag_bounded(int idx, int expect) {
    __shared__ int sdone;
    if (threadIdx.x == 0) {
        int it = 0;
        while (((volatile int*)g_bar)[idx] < expect && it < 200000) {
            __nanosleep(128); it++;
        }
        sdone = (((volatile int*)g_bar)[idx] >= expect) ? 1 : 0;
    }
    __syncthreads();
    __threadfence();
    return sdone != 0;
}

// ---------------- k1: init (scratch + aux copies + edge fill) ----------------
__global__ void k_init(const int* __restrict__ cci, const float* __restrict__ dist,
                       float* __restrict__ out) {
    int i = blockIdx.x * blockDim.x + threadIdx.x;   // 262144 threads
    if (i < NKEYS) g_cnt_key[i] = 0;
    if (i < NCEN)  g_cnt_node[i] = 0;
    if (i < 2 * EC1) out[O_EDGES + i] = -1.0f;
    if (i < NN) {
        out[O_CCI + i]  = (float)cci[i];
        out[O_DIST + i] = dist[i];
    }
    if (i < 8) g_bar[i] = 0;
    if (i == 8) g_work = 0;
}

// ---- barrier map: 0 edgekey, 1 scan1, 2 scan2, 3 scan3+pad, 6 sort-done,
//      4 mlp-zero+hist, 5 mlp-adds-done ----

// ---------------- k_edge: edgekey -> scan1 -> scan2 -> scan3 -> sort ---------
#define FB 74
__global__ __launch_bounds__(512, 2)
void k_edge(const int* __restrict__ ei, const int* __restrict__ cci,
            float* __restrict__ out) {
    __shared__ int so[16], sc[16];
    int t = threadIdx.x, lane = t & 31, wid = t >> 5;
    int gid = blockIdx.x * 512 + t;

    // ---- edge keys + per-key counts ----
    for (int e = gid; e < EE; e += FB * 512) {
        int s = cci[ei[e]];
        int v = cci[ei[EE + e]];
        if (s == v) { g_key[e] = -1; continue; }
        int a = min(s, v), b = max(s, v);
        int key = a * NCEN + b;
        g_key[e] = key;
        atomicAdd(&g_cnt_key[key], 1);
    }
    gbarrier(0, FB, true);

    // ---- scan1: per-tile sums ----
    for (int tb = blockIdx.x; tb < 512; tb += FB) {
        int cnt = g_cnt_key[tb * 512 + t];
        int occ = (cnt > 0);
        int wo = __reduce_add_sync(0xffffffffu, occ);
        int wc = __reduce_add_sync(0xffffffffu, cnt);
        if (lane == 0) { so[wid] = wo; sc[wid] = wc; }
        __syncthreads();
        if (t < 32) {
            int vo = (lane < 16) ? so[lane] : 0;
            int vc = (lane < 16) ? sc[lane] : 0;
            vo = __reduce_add_sync(0xffffffffu, vo);
            vc = __reduce_add_sync(0xffffffffu, vc);
            if (lane == 0) { g_blk_occ[tb] = vo; g_blk_cnt[tb] = vc; }
        }
        __syncthreads();
    }
    gbarrier(1, FB, blockIdx.x == 0);

    // ---- scan2 (block 0) ----
    if (blockIdx.x == 0) {
        int vo = g_blk_occ[t], vc = g_blk_cnt[t];
        int io = wscan_incl(vo, lane);
        int ic = wscan_incl(vc, lane);
        if (lane == 31) { so[wid] = io; sc[wid] = ic; }
        __syncthreads();
        if (t < 32) {
            int a = (lane < 16) ? so[lane] : 0;
            int b = (lane < 16) ? sc[lane] : 0;
            int ia = wscan_incl(a, lane);
            int ib = wscan_incl(b, lane);
            if (lane < 16) { so[lane] = ia - a; sc[lane] = ib - b; }
            if (lane == 15) { g_nuniq = ia; g_totedge = ib; }
        }
        __syncthreads();
        g_blk_occ[t] = io - vo + so[wid];
        g_blk_cnt[t] = ic - vc + sc[wid];
    }
    gbarrier(2, FB, true);   // all wait for scan2

    // ---- scan3: per-key slot/offset + coarse_edges write ----
    for (int tb = blockIdx.x; tb < 512; tb += FB) {
        int key = tb * 512 + t;
        int cnt = g_cnt_key[key];
        int occ = (cnt > 0);
        int io = wscan_incl(occ, lane);
        int ic = wscan_incl(cnt, lane);
        if (lane == 31) { so[wid] = io; sc[wid] = ic; }
        __syncthreads();
        if (t < 32) {
            int a = (lane < 16) ? so[lane] : 0;
            int b = (lane < 16) ? sc[lane] : 0;
            int ia = wscan_incl(a, lane);
            int ib = wscan_incl(b, lane);
            if (lane < 16) { so[lane] = ia - a; sc[lane] = ib - b; }
        }
        __syncthreads();
        int occ_ex = io - occ + so[wid] + g_blk_occ[tb];
        int cnt_ex = ic - cnt + sc[wid] + g_blk_cnt[tb];
        g_cursor[key] = cnt_ex;
        if (occ) {
            g_slot_cnt[occ_ex] = cnt;
            g_slot_off[occ_ex] = cnt_ex;
            out[O_EDGES + occ_ex]       = (float)(key >> 9);
            out[O_EDGES + EC1 + occ_ex] = (float)(key & 511);
        }
        __syncthreads();
    }

    // ---- zero unoccupied attr slots ----
    {
        int nu = g_nuniq;
        float4 z = make_float4(0.f, 0.f, 0.f, 0.f);
        float4* p = (float4*)(out + O_ATTR);
        for (int slot = nu + blockIdx.x; slot < EC1; slot += FB) {
            if (t < 32)      p[(size_t)slot * 32 + t] = z;
            else if (t < 64) p[((size_t)EC1 + slot) * 32 + (t - 32)] = z;
        }
    }
    gbarrier(3, FB, true);

    // ---- counting-sort scatter ----
    for (int e = blockIdx.x * 512 + t; e < EE; e += FB * 512) {
        int key = g_key[e];
        if (key < 0) continue;
        int pos = atomicAdd(&g_cursor[key], 1);
        g_edge_sorted[pos] = e;
    }

    // sort-done flag
    __threadfence();
    __syncthreads();
    if (t == 0) atomicAdd(&g_bar[6], 1);
}

// =====================================================================
// ACC worker: pull CHUNK-slot ranges from the shared g_work pool.
// 8 warps per caller block, 8KB ring per warp.
// =====================================================================
#define CHUNK 8
#define RING 8

__device__ __noinline__ void acc_worker(char* wbase, uint32_t wbase_s, int lane,
                                        const float4* __restrict__ ea4,
                                        float4* __restrict__ o) {
    int nu = g_nuniq;
    for (int it = 0; it < 32768; it++) {     // bound: nu/CHUNK <= 16353
        int s0;
        if (lane == 0) s0 = atomicAdd(&g_work, CHUNK);
        s0 = __shfl_sync(0xffffffffu, s0, 0);
        if (s0 >= nu) return;
        int S1 = min(s0 + CHUNK, nu);
        int E0 = g_slot_off[s0];
        int E1 = (S1 < nu) ? g_slot_off[S1] : g_totedge;

        int c_l = (s0 + lane < S1) ? g_slot_cnt[s0 + lane] : 0;
        int pe = E0, sub = 32, produced = 0, consumed = 0;
        int pslot = 0, cslot = 0;
        int e_l = 0;

        for (int s = s0; s < S1; s++) {
            int cnt = __shfl_sync(0xffffffffu, c_l, s - s0);
            float4 s0v = make_float4(0.f, 0.f, 0.f, 0.f);
            float4 s1v = make_float4(0.f, 0.f, 0.f, 0.f);
            for (int j = 0; j < cnt; j++) {
                while (pe < E1 && produced - consumed < RING - 1) {
                    if (sub == 32) {
                        e_l = (pe + lane < E1) ? g_edge_sorted[pe + lane] : 0;
                        sub = 0;
                    }
                    int e = __shfl_sync(0xffffffffu, e_l, sub);
                    uint32_t dst = wbase_s + pslot * 1024 + lane * 16;
                    cp16(dst,       &ea4[(size_t)e * 32 + lane]);
                    cp16(dst + 512, &ea4[((size_t)EE + e) * 32 + lane]);
                    CP_COMMIT();
                    produced++; pe++; sub++;
                    pslot = (pslot + 1 == RING) ? 0 : pslot + 1;
                }
                if (produced - consumed >= RING - 1) { CP_WAIT(RING - 2); }
                else                                 { CP_WAIT(0); }
                const char* sp = wbase + cslot * 1024 + lane * 16;
                float4 v0 = *(const float4*)sp;
                float4 v1 = *(const float4*)(sp + 512);
                consumed++;
                cslot = (cslot + 1 == RING) ? 0 : cslot + 1;
                s0v.x += v0.x; s0v.y += v0.y; s0v.z += v0.z; s0v.w += v0.w;
                s1v.x += v1.x; s1v.y += v1.y; s1v.z += v1.z; s1v.w += v1.w;
            }
            float inv = 1.0f / (float)cnt;
            o[(size_t)s * 32 + lane] =
                make_float4(s0v.x * inv, s0v.y * inv, s0v.z * inv, s0v.w * inv);
            o[((size_t)EC1 + s) * 32 + lane] =
                make_float4(s1v.x * inv, s1v.y * inv, s1v.z * inv, s1v.w * inv);
        }
    }
}

// =====================================================================
// k_acc: 296 CTAs x 256 thr, 8 warps x 8KB rings (64KB smem) — one CTA
// fits NEXT TO the two resident mlp CTAs, so edge streaming starts
// while the MLP is still running. Can drain the whole pool alone.
// =====================================================================
#define ACC_SMEM (8 * RING * 1024)   // 65536
__global__ __launch_bounds__(256, 1)
void k_acc(const float* __restrict__ ea, float* __restrict__ out) {
    int t = threadIdx.x;
    int wid = t >> 5, lane = t & 31;
    extern __shared__ char smraw[];
    char* wbase = smraw + wid * (RING * 1024);
    uint32_t wbase_s = (uint32_t)__cvta_generic_to_shared(wbase);
    acc_worker(wbase, wbase_s, lane, (const float4*)ea, (float4*)(out + O_ATTR));
}

// =====================================================================
// k_mlp: 296 CTAs (2/SM), column-split GEMM. Each CTA: 64-node x 64-col
// tiles, W-half 32KB + x tile 33.8KB = 66.5KB smem, ~80 regs.
// zero+hist -> tiles -> divide -> optional pool join.
// =====================================================================
#define TILE_N 64
#define XS_LD  132
#define TILES_PER_B 1563
#define TOT_TILES (2 * TILES_PER_B)
#define MLP_SMEM (32768 + TILE_N * XS_LD * 4)   // 66560
#define MLP_CTAS 296

__global__ __launch_bounds__(256, 3)
void k_mlp(const float* __restrict__ x, const float* __restrict__ dist,
           const float* __restrict__ W, const float* __restrict__ bias,
           const int* __restrict__ cci, const float* __restrict__ ea,
           float* __restrict__ out) {
    int t = threadIdx.x;
    int wid = t >> 5, lane = t & 31;
    extern __shared__ char smraw[];

    // phase 0: zero node region + node histogram (this kernel owns both)
    for (int i = blockIdx.x * 256 + t; i < 2 * NCEN * HH; i += MLP_CTAS * 256)
        out[O_NODE + i] = 0.0f;
    for (int n = blockIdx.x * 256 + t; n < NN; n += MLP_CTAS * 256)
        atomicAdd(&g_cnt_node[cci[n]], 1);
    gbarrier(4, MLP_CTAS, true);

    {
        unsigned long long* Wp = (unsigned long long*)smraw;   // [64 kp][64 col]
        float* xs = (float*)(smraw + 32768);                   // 64*132 floats

        int pair    = blockIdx.x >> 1;
        int colbase = (blockIdx.x & 1) * 64;

        // pair-transpose W half: Wp[kp][j] = (W[2kp][cb+j], W[2kp+1][cb+j])
        for (int idx = t; idx < 64 * 64; idx += 256) {
            int kp = idx >> 6, j = idx & 63;
            float a = W[(2 * kp) * HH + colbase + j];
            float b = W[(2 * kp + 1) * HH + colbase + j];
            Wp[idx] = pack2(a, b);
        }

        int colb  = lane * 2;            // local cols [0,64)
        int nodeb = wid * 8;

        float w128[2], bl[2];
#pragma unroll
        for (int c = 0; c < 2; c++) {
            w128[c] = __ldg(&W[128 * HH + colbase + colb + c]);
            bl[c]   = __ldg(&bias[colbase + colb + c]);
        }
        __syncthreads();

        for (int tile = pair; tile < TOT_TILES; tile += 148) {
            int b  = tile / TILES_PER_B;
            int n0 = (tile - b * TILES_PER_B) * TILE_N;
            __syncthreads();
#pragma unroll
            for (int r = 0; r < 8; r++) {
                int idx = r * 256 + t;
                int node = idx >> 5, q = idx & 31;
                int n = n0 + node;
                float4 v = make_float4(0.f, 0.f, 0.f, 0.f);
                if (n < NN) v = *(const float4*)&x[((size_t)b * NN + n) * HH + q * 4];
                *(float4*)&xs[node * XS_LD + q * 4] = v;
            }
            if (t < TILE_N) {
                int n = n0 + t;
                xs[t * XS_LD + 128] = (n < NN) ? dist[n] : 0.0f;
            }
            __syncthreads();

            unsigned long long acc[8][2];
#pragma unroll
            for (int i = 0; i < 8; i++) { acc[i][0] = 0ull; acc[i][1] = 0ull; }

#pragma unroll 4
            for (int k4 = 0; k4 < 32; k4++) {
                ulonglong2 wA = *(const ulonglong2*)&Wp[(2 * k4) * 64 + colb];
                ulonglong2 wB = *(const ulonglong2*)&Wp[(2 * k4 + 1) * 64 + colb];
#pragma unroll
                for (int i = 0; i < 8; i++) {
                    ulonglong2 xv =
                        *(const ulonglong2*)&xs[(nodeb + i) * XS_LD + 4 * k4];
                    fma2(acc[i][0], xv.x, wA.x);
                    fma2(acc[i][1], xv.x, wA.y);
                    fma2(acc[i][0], xv.y, wB.x);
                    fma2(acc[i][1], xv.y, wB.y);
                }
            }

#pragma unroll
            for (int i = 0; i < 8; i++) {
                int n = n0 + nodeb + i;
                if (n >= NN) continue;
                float d = xs[(nodeb + i) * XS_LD + 128];
                int cc = cci[n];
                float* ob = out + ((size_t)b * NCEN + cc) * HH + colbase + colb;
                float2 p0 = unpack2(acc[i][0]);
                float2 p1 = unpack2(acc[i][1]);
                float v0 = fmaxf(p0.x + p0.y + d * w128[0] + bl[0], 0.0f);
                float v1 = fmaxf(p1.x + p1.y + d * w128[1] + bl[1], 0.0f);
                red_add_v2(ob, v0, v1);
            }
        }
        __syncthreads();
    }

    // phase 2: all MLP adds done -> node mean divide
    gbarrier(5, MLP_CTAS, true);
    for (int i = blockIdx.x * 256 + t; i < 2 * NCEN * HH; i += MLP_CTAS * 256) {
        int c = (i >> 7) & (NCEN - 1);
        out[i] *= 1.0f / (float)max(g_cnt_node[c], 1);
    }

    // phase 3: OPTIONAL pool join (bounded wait -> no deadlock; k_acc can
    // drain the pool alone if this times out under profiler serialization).
    if (!wait_flag_bounded(6, FB)) return;
    char* wbase = smraw + wid * (RING * 1024);   // 8 x 8KB = 64KB <= 66560
    uint32_t wbase_s = (uint32_t)__cvta_generic_to_shared(wbase);
    acc_worker(wbase, wbase_s, lane, (const float4*)ea, (float4*)(out + O_ATTR));
}

// ---------------- launch ----------------
extern "C" void kernel_launch(void* const* d_in, const int* in_sizes, int n_in,
                              void* d_out, int out_size) {
    const float* x    = (const float*)d_in[0];
    const int*   ei   = (const int*)d_in[1];
    const float* ea   = (const float*)d_in[2];
    const int*   cci  = (const int*)d_in[4];
    const float* dist = (const float*)d_in[5];
    const float* W    = (const float*)d_in[6];
    const float* bias = (const float*)d_in[7];
    float* out = (float*)d_out;

    static cudaStream_t s2 = nullptr;
    static cudaEvent_t evF = nullptr, evJ = nullptr;
    if (!s2) {
        cudaStreamCreateWithFlags(&s2, cudaStreamNonBlocking);
        cudaEventCreateWithFlags(&evF, cudaEventDisableTiming);
        cudaEventCreateWithFlags(&evJ, cudaEventDisableTiming);
        cudaFuncSetAttribute(k_mlp, cudaFuncAttributeMaxDynamicSharedMemorySize, MLP_SMEM);
        cudaFuncSetAttribute(k_acc, cudaFuncAttributeMaxDynamicSharedMemorySize, ACC_SMEM);
    }

    k_init<<<1024, 256>>>(cci, dist, out);

    // fork right after init: node path on s2, edge path on stream 0
    cudaEventRecord(evF, 0);
    cudaStreamWaitEvent(s2, evF, 0);
    k_mlp<<<MLP_CTAS, 256, MLP_SMEM, s2>>>(x, dist, W, bias, cci, ea, out);
    cudaEventRecord(evJ, s2);

    k_edge<<<FB, 512>>>(ei, cci, out);
    k_acc<<<296, 256, ACC_SMEM>>>(ea, out);

    cudaStreamWaitEvent(0, evJ, 0);   // join: harness syncs stream 0
}